// round 7
// baseline (speedup 1.0000x reference)
#include <cuda_runtime.h>

// GRU final-hidden for B=8192 sequences, H=3, I=1, T=2048.
// One thread per batch element; serial recurrence over its own seq length
// (h is frozen after seq_len, so we simply stop early).
//
// Math folding:
//  sigmoid(a) = 0.5*tanh(0.5*a) + 0.5
//  r/z rows: matvec with weights pre-scaled by 0.5 and bias' = 0.5*(b_ih+b_hh)
//            directly yields 0.5*(xg+hg); t = tanh.approx of that.
//  n row:    s = 0.5*hn (0.5-scaled weights, bias 0.5*b_hh, no x term)
//            n_arg = xn + r*hn = (xn + s) + t_r*s
//  update:   u = z*h = fma(t_z, h/2, h/2); v = 1-z = fma(-0.5, t_z, 0.5)
//            h' = fma(v, n, u)
// FMA-pipe pressure halved with packed fma.rn.f32x2 (FFMA2) inline PTX.
// Matvec accumulations are tree-structured (two 2-deep chains + add).
// MUFU pipe (9 tanh.approx x rt 8 = 72 cyc/step/SMSP) is the predicted bound.

typedef unsigned long long u64;

__device__ __forceinline__ u64 pk2(float a, float b) {
    u64 r; asm("mov.b64 %0, {%1, %2};" : "=l"(r) : "f"(a), "f"(b)); return r;
}
__device__ __forceinline__ void upk2(u64 v, float& a, float& b) {
    asm("mov.b64 {%0, %1}, %2;" : "=f"(a), "=f"(b) : "l"(v));
}
__device__ __forceinline__ u64 fma2(u64 a, u64 b, u64 c) {
    u64 d; asm("fma.rn.f32x2 %0, %1, %2, %3;" : "=l"(d) : "l"(a), "l"(b), "l"(c)); return d;
}
__device__ __forceinline__ u64 add2(u64 a, u64 b) {
    u64 d; asm("add.rn.f32x2 %0, %1, %2;" : "=l"(d) : "l"(a), "l"(b)); return d;
}
__device__ __forceinline__ u64 mul2(u64 a, u64 b) {
    u64 d; asm("mul.rn.f32x2 %0, %1, %2;" : "=l"(d) : "l"(a), "l"(b)); return d;
}
__device__ __forceinline__ float tanh_fast(float x) {
    float r; asm("tanh.approx.f32 %0, %1;" : "=f"(r) : "f"(x)); return r;
}

__global__ void __launch_bounds__(64)
gru_final_hidden_kernel(const float* __restrict__ x,
                        const int*   __restrict__ lens,
                        const float* __restrict__ h0g,
                        const float* __restrict__ Wih,   // [9,1]
                        const float* __restrict__ Whh,   // [9,3]
                        const float* __restrict__ bih,   // [9]
                        const float* __restrict__ bhh,   // [9]
                        float* __restrict__ out,         // [1,B,3]
                        int Bn, int Tn)
{
    const int b = blockIdx.x * blockDim.x + threadIdx.x;
    if (b >= Bn) return;

    // ---- load + preprocess weights (uniform across threads, L1/L2 broadcast) ----
    float wih[9], whh[9][3], vbih[9], vbhh[9];
#pragma unroll
    for (int i = 0; i < 9; i++) {
        wih[i]  = Wih[i];
        vbih[i] = bih[i];
        vbhh[i] = bhh[i];
#pragma unroll
        for (int k = 0; k < 3; k++) whh[i][k] = Whh[i * 3 + k];
    }

    // r/z rows (0..5): weights*0.5, bias' = 0.5*(bih+bhh), x-weight*0.5
    float ws[6][3], bx[6], wxs[6];
#pragma unroll
    for (int r = 0; r < 6; r++) {
        bx[r]  = 0.5f * (vbih[r] + vbhh[r]);
        wxs[r] = 0.5f * wih[r];
#pragma unroll
        for (int k = 0; k < 3; k++) ws[r][k] = 0.5f * whh[r][k];
    }
    // n rows (6..8): s = 0.5*hn -> weights*0.5, bias 0.5*bhh (NO x, NO bih)
    float wn[3][3], bn[3];
#pragma unroll
    for (int j = 0; j < 3; j++) {
        bn[j] = 0.5f * vbhh[6 + j];
#pragma unroll
        for (int k = 0; k < 3; k++) wn[j][k] = 0.5f * whh[6 + j][k];
    }

    // Packed constants: A=(row0,row1) B=(row2,row3) C=(row4,row5) N=(row6,row7), scalar row8
    u64 wA[3], wB[3], wC[3], wN[3];
#pragma unroll
    for (int k = 0; k < 3; k++) {
        wA[k] = pk2(ws[0][k], ws[1][k]);
        wB[k] = pk2(ws[2][k], ws[3][k]);
        wC[k] = pk2(ws[4][k], ws[5][k]);
        wN[k] = pk2(wn[0][k], wn[1][k]);
    }
    const u64 bA  = pk2(bx[0], bx[1]);
    const u64 bB  = pk2(bx[2], bx[3]);
    const u64 bC  = pk2(bx[4], bx[5]);
    const u64 bN  = pk2(bn[0], bn[1]);
    const u64 wAx = pk2(wxs[0], wxs[1]);
    const u64 wBx = pk2(wxs[2], wxs[3]);
    const u64 wCx = pk2(wxs[4], wxs[5]);
    const u64 wxN = pk2(wih[6], wih[7]);
    const u64 bxN = pk2(vbih[6], vbih[7]);
    const float wn8_0 = wn[2][0], wn8_1 = wn[2][1], wn8_2 = wn[2][2], bn8 = bn[2];
    const float wx8 = wih[8], bx8 = vbih[8];
    const u64 HALF2  = pk2(0.5f, 0.5f);
    const u64 NHALF2 = pk2(-0.5f, -0.5f);

    // ---- state ----
    float h0s = h0g[b * 3 + 0];
    float h1s = h0g[b * 3 + 1];
    float h2s = h0g[b * 3 + 2];

    int len = lens[b];
    if (len < 0) len = 0;
    if (len > Tn) len = Tn;

    // Tree matvec: p = fma(w0,h0, fma(wx,x,bias)) (depth 2) in parallel with
    // q = fma(w2,h2, mul(w1,h1)) (depth 2), then add (depth 3 = 12 cyc).
#define GSTEP(XV)                                                              \
    {                                                                          \
        const float xv_ = (XV);                                                \
        u64 bh0 = pk2(h0s, h0s), bh1 = pk2(h1s, h1s), bh2 = pk2(h2s, h2s);     \
        u64 xx = pk2(xv_, xv_);                                                \
        u64 aAp = fma2(wA[0], bh0, fma2(wAx, xx, bA));                         \
        u64 aAq = fma2(wA[2], bh2, mul2(wA[1], bh1));                          \
        u64 aBp = fma2(wB[0], bh0, fma2(wBx, xx, bB));                         \
        u64 aBq = fma2(wB[2], bh2, mul2(wB[1], bh1));                          \
        u64 aCp = fma2(wC[0], bh0, fma2(wCx, xx, bC));                         \
        u64 aCq = fma2(wC[2], bh2, mul2(wC[1], bh1));                          \
        u64 sNp = fma2(wN[0], bh0, bN);                                        \
        u64 sNq = fma2(wN[2], bh2, mul2(wN[1], bh1));                          \
        u64 aA = add2(aAp, aAq);                                               \
        u64 aB = add2(aBp, aBq);                                               \
        u64 aC = add2(aCp, aCq);                                               \
        u64 sN = add2(sNp, sNq);                                               \
        float s8p = fmaf(wn8_0, h0s, bn8);                                     \
        float s8q = fmaf(wn8_2, h2s, wn8_1 * h1s);                             \
        float s8 = s8p + s8q;                                                  \
        u64 xnp = add2(fma2(wxN, xx, bxN), sN);                                \
        float xnp8 = fmaf(wx8, xv_, bx8) + s8;                                 \
        float a0, a1, a2, a3, a4, a5;                                          \
        upk2(aA, a0, a1); upk2(aB, a2, a3); upk2(aC, a4, a5);                  \
        float tr0 = tanh_fast(a0), tr1 = tanh_fast(a1), tr2 = tanh_fast(a2);   \
        float tz0 = tanh_fast(a3), tz1 = tanh_fast(a4), tz2 = tanh_fast(a5);   \
        u64 tr01 = pk2(tr0, tr1);                                              \
        u64 narg01 = fma2(tr01, sN, xnp);                                      \
        float narg2 = fmaf(tr2, s8, xnp8);                                     \
        float g0, g1; upk2(narg01, g0, g1);                                    \
        float n0 = tanh_fast(g0), n1 = tanh_fast(g1), n2 = tanh_fast(narg2);   \
        u64 h01 = pk2(h0s, h1s);                                               \
        u64 hh = mul2(h01, HALF2);                                             \
        u64 tz01 = pk2(tz0, tz1);                                              \
        u64 uu = fma2(tz01, hh, hh);                                           \
        u64 vv = fma2(tz01, NHALF2, HALF2);                                    \
        u64 n01 = pk2(n0, n1);                                                 \
        u64 hn01 = fma2(vv, n01, uu);                                          \
        upk2(hn01, h0s, h1s);                                                  \
        float hh2 = 0.5f * h2s;                                                \
        float u2 = fmaf(tz2, hh2, hh2);                                        \
        float v2 = fmaf(-0.5f, tz2, 0.5f);                                     \
        h2s = fmaf(v2, n2, u2);                                                \
    }

    // ---- recurrence: float4 loads along T (16B/sector instead of 4B).
    //      Main loop prefetches v+1 unconditionally; last full chunk and the
    //      remainder are peeled so the hot loop has no clamp arithmetic.
    const float4* xp = reinterpret_cast<const float4*>(x + (size_t)b * (size_t)Tn);
    const int nv  = len >> 2;    // full float4 chunks
    const int rem = len & 3;

    if (nv > 0) {
        float4 cur = __ldg(xp);
        // chunks 0 .. nv-2: prefetch next chunk unconditionally
        for (int v = 0; v < nv - 1; ++v) {
            float4 nxt = __ldg(xp + v + 1);
            GSTEP(cur.x);
            GSTEP(cur.y);
            GSTEP(cur.z);
            GSTEP(cur.w);
            cur = nxt;
        }
        // last full chunk: prefetch remainder chunk if it exists
        float4 tail = (rem > 0) ? __ldg(xp + nv) : cur;
        GSTEP(cur.x);
        GSTEP(cur.y);
        GSTEP(cur.z);
        GSTEP(cur.w);
        if (rem > 0) {
            GSTEP(tail.x);
            if (rem > 1) GSTEP(tail.y);
            if (rem > 2) GSTEP(tail.z);
        }
    } else if (rem > 0) {
        float4 tail = __ldg(xp);
        GSTEP(tail.x);
        if (rem > 1) GSTEP(tail.y);
        if (rem > 2) GSTEP(tail.z);
    }
#undef GSTEP

    // ---- output: sigmoid(h_final), accurate path (ex2.approx ~2^-22) ----
    out[b * 3 + 0] = 1.0f / (1.0f + __expf(-h0s));
    out[b * 3 + 1] = 1.0f / (1.0f + __expf(-h1s));
    out[b * 3 + 2] = 1.0f / (1.0f + __expf(-h2s));
}

extern "C" void kernel_launch(void* const* d_in, const int* in_sizes, int n_in,
                              void* d_out, int out_size)
{
    const float* x    = (const float*)d_in[0];
    const int*   lens = (const int*)  d_in[1];
    const float* h0   = (const float*)d_in[2];
    const float* Wih  = (const float*)d_in[3];
    const float* Whh  = (const float*)d_in[4];
    const float* bih  = (const float*)d_in[5];
    const float* bhh  = (const float*)d_in[6];
    float* out = (float*)d_out;

    const int Bn = in_sizes[1];                 // 8192
    const int Tn = in_sizes[0] / Bn;            // 2048 (I=1)

    const int threads = 64;
    const int blocks  = (Bn + threads - 1) / threads;
    gru_final_hidden_kernel<<<blocks, threads>>>(x, lens, h0, Wih, Whh, bih, bhh,
                                                 out, Bn, Tn);
}

// round 16
// speedup vs baseline: 1.0281x; 1.0281x over previous
#include <cuda_runtime.h>

// GRU final-hidden for B=8192 sequences, H=3, I=1, T=2048.
// One thread per batch element; serial recurrence over its own seq length.
//
// R7 measured: 139.4us, 136 cyc/step = issue(72) + ~64 exposed chain stalls.
// R8 change: hoist all x-only affine terms per float4 chunk (off-chain work
// made explicitly schedulable into the tanh-chain stall cycles) and unlock
// registers via __launch_bounds__(64,1) so ptxas can keep them live.
//
// Math folding (unchanged, verified rel_err 4.5e-7):
//  sigmoid(a) = 0.5*tanh(0.5*a) + 0.5
//  r/z rows: 0.5-scaled weights/biases -> tanh of 0.5*(xg+hg)
//  n row:    s = 0.5*hn; n_arg = (xn + s) + t_r*s
//  update:   u = fma(t_z, h/2, h/2); v = fma(-0.5, t_z, 0.5); h' = fma(v,n,u)

typedef unsigned long long u64;

__device__ __forceinline__ u64 pk2(float a, float b) {
    u64 r; asm("mov.b64 %0, {%1, %2};" : "=l"(r) : "f"(a), "f"(b)); return r;
}
__device__ __forceinline__ void upk2(u64 v, float& a, float& b) {
    asm("mov.b64 {%0, %1}, %2;" : "=f"(a), "=f"(b) : "l"(v));
}
__device__ __forceinline__ u64 fma2(u64 a, u64 b, u64 c) {
    u64 d; asm("fma.rn.f32x2 %0, %1, %2, %3;" : "=l"(d) : "l"(a), "l"(b), "l"(c)); return d;
}
__device__ __forceinline__ u64 add2(u64 a, u64 b) {
    u64 d; asm("add.rn.f32x2 %0, %1, %2;" : "=l"(d) : "l"(a), "l"(b)); return d;
}
__device__ __forceinline__ u64 mul2(u64 a, u64 b) {
    u64 d; asm("mul.rn.f32x2 %0, %1, %2;" : "=l"(d) : "l"(a), "l"(b)); return d;
}
__device__ __forceinline__ float tanh_fast(float x) {
    float r; asm("tanh.approx.f32 %0, %1;" : "=f"(r) : "f"(x)); return r;
}

__global__ void __launch_bounds__(64, 1)
gru_final_hidden_kernel(const float* __restrict__ x,
                        const int*   __restrict__ lens,
                        const float* __restrict__ h0g,
                        const float* __restrict__ Wih,   // [9,1]
                        const float* __restrict__ Whh,   // [9,3]
                        const float* __restrict__ bih,   // [9]
                        const float* __restrict__ bhh,   // [9]
                        float* __restrict__ out,         // [1,B,3]
                        int Bn, int Tn)
{
    const int b = blockIdx.x * blockDim.x + threadIdx.x;
    if (b >= Bn) return;

    // ---- load + preprocess weights (uniform, L1/L2 broadcast) ----
    float wih[9], whh[9][3], vbih[9], vbhh[9];
#pragma unroll
    for (int i = 0; i < 9; i++) {
        wih[i]  = Wih[i];
        vbih[i] = bih[i];
        vbhh[i] = bhh[i];
#pragma unroll
        for (int k = 0; k < 3; k++) whh[i][k] = Whh[i * 3 + k];
    }

    float ws[6][3], bx[6], wxs[6];
#pragma unroll
    for (int r = 0; r < 6; r++) {
        bx[r]  = 0.5f * (vbih[r] + vbhh[r]);
        wxs[r] = 0.5f * wih[r];
#pragma unroll
        for (int k = 0; k < 3; k++) ws[r][k] = 0.5f * whh[r][k];
    }
    float wn[3][3], bn[3];
#pragma unroll
    for (int j = 0; j < 3; j++) {
        bn[j] = 0.5f * vbhh[6 + j];
#pragma unroll
        for (int k = 0; k < 3; k++) wn[j][k] = 0.5f * whh[6 + j][k];
    }

    u64 wA[3], wB[3], wC[3], wN[3];
#pragma unroll
    for (int k = 0; k < 3; k++) {
        wA[k] = pk2(ws[0][k], ws[1][k]);
        wB[k] = pk2(ws[2][k], ws[3][k]);
        wC[k] = pk2(ws[4][k], ws[5][k]);
        wN[k] = pk2(wn[0][k], wn[1][k]);
    }
    const u64 bA  = pk2(bx[0], bx[1]);
    const u64 bB  = pk2(bx[2], bx[3]);
    const u64 bC  = pk2(bx[4], bx[5]);
    const u64 bN  = pk2(bn[0], bn[1]);
    const u64 wAx = pk2(wxs[0], wxs[1]);
    const u64 wBx = pk2(wxs[2], wxs[3]);
    const u64 wCx = pk2(wxs[4], wxs[5]);
    const u64 wxN = pk2(wih[6], wih[7]);
    const u64 bxN = pk2(vbih[6], vbih[7]);
    const float wn8_0 = wn[2][0], wn8_1 = wn[2][1], wn8_2 = wn[2][2], bn8 = bn[2];
    const float wx8 = wih[8], bx8 = vbih[8];
    const u64 HALF2  = pk2(0.5f, 0.5f);
    const u64 NHALF2 = pk2(-0.5f, -0.5f);

    // ---- state ----
    float h0s = h0g[b * 3 + 0];
    float h1s = h0g[b * 3 + 1];
    float h2s = h0g[b * 3 + 2];

    int len = lens[b];
    if (len < 0) len = 0;
    if (len > Tn) len = Tn;

    // Precompute all x-only affine terms for one substep (OFF the h-chain;
    // issued into the previous substep's tanh stalls).
#define PRECOMP(XV, AX, BX, CX, XN, X8)                                        \
    {                                                                          \
        const float xv_ = (XV);                                                \
        u64 xx = pk2(xv_, xv_);                                                \
        AX = fma2(wAx, xx, bA);                                                \
        BX = fma2(wBx, xx, bB);                                                \
        CX = fma2(wCx, xx, bC);                                                \
        XN = fma2(wxN, xx, bxN);                                               \
        X8 = fmaf(wx8, xv_, bx8);                                              \
    }

    // GRU step consuming precomputed x-terms; only h-dependent work inside.
#define GSTEP(AX, BX, CX, XN, X8)                                              \
    {                                                                          \
        u64 bh0 = pk2(h0s, h0s), bh1 = pk2(h1s, h1s), bh2 = pk2(h2s, h2s);     \
        u64 aAp = fma2(wA[0], bh0, AX);                                        \
        u64 aAq = fma2(wA[2], bh2, mul2(wA[1], bh1));                          \
        u64 aBp = fma2(wB[0], bh0, BX);                                        \
        u64 aBq = fma2(wB[2], bh2, mul2(wB[1], bh1));                          \
        u64 aCp = fma2(wC[0], bh0, CX);                                        \
        u64 aCq = fma2(wC[2], bh2, mul2(wC[1], bh1));                          \
        u64 sNp = fma2(wN[0], bh0, bN);                                        \
        u64 sNq = fma2(wN[2], bh2, mul2(wN[1], bh1));                          \
        u64 aA = add2(aAp, aAq);                                               \
        u64 aB = add2(aBp, aBq);                                               \
        u64 aC = add2(aCp, aCq);                                               \
        u64 sN = add2(sNp, sNq);                                               \
        float s8p = fmaf(wn8_0, h0s, bn8);                                     \
        float s8q = fmaf(wn8_2, h2s, wn8_1 * h1s);                             \
        float s8 = s8p + s8q;                                                  \
        u64 xnp = add2(XN, sN);                                                \
        float xnp8 = (X8) + s8;                                                \
        float a0, a1, a2, a3, a4, a5;                                          \
        upk2(aA, a0, a1); upk2(aB, a2, a3); upk2(aC, a4, a5);                  \
        float tr0 = tanh_fast(a0), tr1 = tanh_fast(a1), tr2 = tanh_fast(a2);   \
        float tz0 = tanh_fast(a3), tz1 = tanh_fast(a4), tz2 = tanh_fast(a5);   \
        u64 tr01 = pk2(tr0, tr1);                                              \
        u64 narg01 = fma2(tr01, sN, xnp);                                      \
        float narg2 = fmaf(tr2, s8, xnp8);                                     \
        float g0, g1; upk2(narg01, g0, g1);                                    \
        float n0 = tanh_fast(g0), n1 = tanh_fast(g1), n2 = tanh_fast(narg2);   \
        u64 h01 = pk2(h0s, h1s);                                               \
        u64 hh = mul2(h01, HALF2);                                             \
        u64 tz01 = pk2(tz0, tz1);                                              \
        u64 uu = fma2(tz01, hh, hh);                                           \
        u64 vv = fma2(tz01, NHALF2, HALF2);                                    \
        u64 n01 = pk2(n0, n1);                                                 \
        u64 hn01 = fma2(vv, n01, uu);                                          \
        upk2(hn01, h0s, h1s);                                                  \
        float hh2 = 0.5f * h2s;                                                \
        float u2 = fmaf(tz2, hh2, hh2);                                        \
        float v2 = fmaf(-0.5f, tz2, 0.5f);                                     \
        h2s = fmaf(v2, n2, u2);                                                \
    }

    // Process one float4 chunk: precompute x-terms for all 4 substeps first
    // (independent of h -> fills stall cycles), then run 4 serial steps.
#define CHUNK4(CC)                                                             \
    {                                                                          \
        u64 AX0, BX0, CX0, XN0; float X80;                                     \
        u64 AX1, BX1, CX1, XN1; float X81;                                     \
        u64 AX2, BX2, CX2, XN2; float X82;                                     \
        u64 AX3, BX3, CX3, XN3; float X83;                                     \
        PRECOMP((CC).x, AX0, BX0, CX0, XN0, X80);                              \
        PRECOMP((CC).y, AX1, BX1, CX1, XN1, X81);                              \
        PRECOMP((CC).z, AX2, BX2, CX2, XN2, X82);                              \
        PRECOMP((CC).w, AX3, BX3, CX3, XN3, X83);                              \
        GSTEP(AX0, BX0, CX0, XN0, X80);                                        \
        GSTEP(AX1, BX1, CX1, XN1, X81);                                        \
        GSTEP(AX2, BX2, CX2, XN2, X82);                                        \
        GSTEP(AX3, BX3, CX3, XN3, X83);                                        \
    }

    const float4* xp = reinterpret_cast<const float4*>(x + (size_t)b * (size_t)Tn);
    const int nv  = len >> 2;    // full float4 chunks
    const int rem = len & 3;

    if (nv > 0) {
        float4 cur = __ldg(xp);
        for (int v = 0; v < nv - 1; ++v) {
            float4 nxt = __ldg(xp + v + 1);
            CHUNK4(cur);
            cur = nxt;
        }
        float4 tail = (rem > 0) ? __ldg(xp + nv) : cur;
        CHUNK4(cur);
        if (rem > 0) {
            u64 AX0, BX0, CX0, XN0; float X80;
            PRECOMP(tail.x, AX0, BX0, CX0, XN0, X80);
            GSTEP(AX0, BX0, CX0, XN0, X80);
            if (rem > 1) {
                u64 AX1, BX1, CX1, XN1; float X81;
                PRECOMP(tail.y, AX1, BX1, CX1, XN1, X81);
                GSTEP(AX1, BX1, CX1, XN1, X81);
            }
            if (rem > 2) {
                u64 AX2, BX2, CX2, XN2; float X82;
                PRECOMP(tail.z, AX2, BX2, CX2, XN2, X82);
                GSTEP(AX2, BX2, CX2, XN2, X82);
            }
        }
    } else if (rem > 0) {
        float4 tail = __ldg(xp);
        u64 AX0, BX0, CX0, XN0; float X80;
        PRECOMP(tail.x, AX0, BX0, CX0, XN0, X80);
        GSTEP(AX0, BX0, CX0, XN0, X80);
        if (rem > 1) {
            u64 AX1, BX1, CX1, XN1; float X81;
            PRECOMP(tail.y, AX1, BX1, CX1, XN1, X81);
            GSTEP(AX1, BX1, CX1, XN1, X81);
        }
        if (rem > 2) {
            u64 AX2, BX2, CX2, XN2; float X82;
            PRECOMP(tail.z, AX2, BX2, CX2, XN2, X82);
            GSTEP(AX2, BX2, CX2, XN2, X82);
        }
    }
#undef CHUNK4
#undef GSTEP
#undef PRECOMP

    // ---- output: sigmoid(h_final), accurate path ----
    out[b * 3 + 0] = 1.0f / (1.0f + __expf(-h0s));
    out[b * 3 + 1] = 1.0f / (1.0f + __expf(-h1s));
    out[b * 3 + 2] = 1.0f / (1.0f + __expf(-h2s));
}

extern "C" void kernel_launch(void* const* d_in, const int* in_sizes, int n_in,
                              void* d_out, int out_size)
{
    const float* x    = (const float*)d_in[0];
    const int*   lens = (const int*)  d_in[1];
    const float* h0   = (const float*)d_in[2];
    const float* Wih  = (const float*)d_in[3];
    const float* Whh  = (const float*)d_in[4];
    const float* bih  = (const float*)d_in[5];
    const float* bhh  = (const float*)d_in[6];
    float* out = (float*)d_out;

    const int Bn = in_sizes[1];                 // 8192
    const int Tn = in_sizes[0] / Bn;            // 2048 (I=1)

    const int threads = 64;
    const int blocks  = (Bn + threads - 1) / threads;
    gru_final_hidden_kernel<<<blocks, threads>>>(x, lens, h0, Wih, Whh, bih, bhh,
                                                 out, Bn, Tn);
}